// round 1
// baseline (speedup 1.0000x reference)
#include <cuda_runtime.h>
#include <math.h>

#define NN   30000
#define EE   480000
#define EP   (EE + NN)      // edges + self loops = 510000
#define INC  128
#define H1   5
#define C1   64
#define F1   (H1 * C1)      // 320
#define OUTC 64
#define PEC  100000
#define NPAIR (2 * PEC)
#define NEG_SLOPE 0.2f

// ---------------- scratch (device globals; no allocs allowed) ----------------
__device__ float g_h1[NN * F1];        // x @ W1
__device__ float g_z1[NN * F1];        // layer1 aggregate -> relu output
__device__ float g_as1[NN * H1];
__device__ float g_ad1[NN * H1];
__device__ float g_m1[NN * H1];
__device__ float g_s1[NN * H1];
__device__ float g_e1[(size_t)EP * H1];
__device__ float g_h2[NN * OUTC];      // z1 @ W2
__device__ float g_z2[NN * OUTC];      // layer2 aggregate -> final embeddings
__device__ float g_as2[NN];
__device__ float g_ad2[NN];
__device__ float g_m2[NN];
__device__ float g_s2[NN];
__device__ float g_e2[EP];

// ---------------- helpers ----------------
__device__ __forceinline__ void atomicMaxFloat(float* addr, float v) {
    // standard sign-split trick; init value is -inf (0xFF800000)
    if (v >= 0.0f) atomicMax((int*)addr, __float_as_int(v));
    else           atomicMin((unsigned int*)addr, __float_as_uint(v));
}

// ---------------- init ----------------
__global__ void init_all(float* z1, float* m1, float* s1,
                         float* z2, float* m2, float* s2) {
    int i = blockIdx.x * blockDim.x + threadIdx.x;
    if (i < NN * F1)  z1[i] = 0.0f;
    if (i < NN * OUTC) z2[i] = 0.0f;
    if (i < NN * H1) { m1[i] = -INFINITY; s1[i] = 0.0f; }
    if (i < NN)      { m2[i] = -INFINITY; s2[i] = 0.0f; }
}

// ---------------- GEMM: C[M,Ncol] = A[M,K] @ B[K,Ncol], row-major ----------------
// 64x64 tile, 256 threads, 4x4 register microtile, BK=16 (K always %16==0).
__global__ void gemm64(const float* __restrict__ A, const float* __restrict__ B,
                       float* __restrict__ C, int M, int Ncol, int K) {
    const int BM = 64, BN = 64, BK = 16, TM = 4, TN = 4;
    __shared__ float As[BK][BM + 4];
    __shared__ float Bs[BK][BN + 4];
    const int tid = threadIdx.x;          // 256
    const int tx  = tid % (BN / TN);      // 0..15
    const int ty  = tid / (BN / TN);      // 0..15
    const int row0 = blockIdx.y * BM;
    const int col0 = blockIdx.x * BN;

    float acc[TM][TN] = {};

    for (int k0 = 0; k0 < K; k0 += BK) {
        // A tile: BM*BK = 1024 elems
        #pragma unroll
        for (int i = tid; i < BM * BK; i += 256) {
            int m = i / BK, k = i % BK;
            int gr = row0 + m;
            As[k][m] = (gr < M) ? A[(size_t)gr * K + (k0 + k)] : 0.0f;
        }
        // B tile: BK*BN = 1024 elems
        #pragma unroll
        for (int i = tid; i < BK * BN; i += 256) {
            int k = i / BN, n = i % BN;
            int gc = col0 + n;
            Bs[k][n] = (gc < Ncol) ? B[(size_t)(k0 + k) * Ncol + gc] : 0.0f;
        }
        __syncthreads();

        #pragma unroll
        for (int k = 0; k < BK; k++) {
            float ra[TM], rb[TN];
            #pragma unroll
            for (int i = 0; i < TM; i++) ra[i] = As[k][ty * TM + i];
            #pragma unroll
            for (int j = 0; j < TN; j++) rb[j] = Bs[k][tx * TN + j];
            #pragma unroll
            for (int i = 0; i < TM; i++)
                #pragma unroll
                for (int j = 0; j < TN; j++)
                    acc[i][j] += ra[i] * rb[j];
        }
        __syncthreads();
    }

    #pragma unroll
    for (int i = 0; i < TM; i++) {
        int r = row0 + ty * TM + i;
        if (r >= M) continue;
        #pragma unroll
        for (int j = 0; j < TN; j++) {
            int c = col0 + tx * TN + j;
            if (c < Ncol) C[(size_t)r * Ncol + c] = acc[i][j];
        }
    }
}

// ---------------- per-node attention logits: a = sum_c h[n,h,c]*att[h,c] ----------------
__global__ void node_att(const float* __restrict__ h,
                         const float* __restrict__ att_s,
                         const float* __restrict__ att_d,
                         float* __restrict__ as_, float* __restrict__ ad_,
                         int H, int C) {
    int idx = blockIdx.x * blockDim.x + threadIdx.x;
    if (idx >= NN * H) return;
    int n = idx / H, hd = idx % H;
    const float4* hr = (const float4*)(h + (size_t)n * H * C + (size_t)hd * C);
    const float4* sr = (const float4*)(att_s + (size_t)hd * C);
    const float4* dr = (const float4*)(att_d + (size_t)hd * C);
    float a = 0.0f, b = 0.0f;
    for (int i = 0; i < C / 4; i++) {
        float4 hv = hr[i], sv = sr[i], dv = dr[i];
        a += hv.x * sv.x + hv.y * sv.y + hv.z * sv.z + hv.w * sv.w;
        b += hv.x * dv.x + hv.y * dv.y + hv.z * dv.z + hv.w * dv.w;
    }
    as_[idx] = a;
    ad_[idx] = b;
}

// ---------------- edge pass A: leaky-relu logits + segment max ----------------
template <int H>
__global__ void edge_logits_max(const int* __restrict__ src, const int* __restrict__ dst,
                                const float* __restrict__ as_, const float* __restrict__ ad_,
                                float* __restrict__ e, float* __restrict__ m) {
    int ee = blockIdx.x * blockDim.x + threadIdx.x;
    if (ee >= EP) return;
    int s = (ee < EE) ? src[ee] : ee - EE;
    int d = (ee < EE) ? dst[ee] : ee - EE;
    #pragma unroll
    for (int h = 0; h < H; h++) {
        float v = as_[s * H + h] + ad_[d * H + h];
        v = (v > 0.0f) ? v : NEG_SLOPE * v;
        e[(size_t)ee * H + h] = v;
        atomicMaxFloat(&m[d * H + h], v);
    }
}

// ---------------- edge pass B: exp(e - m[dst]) + segment sum ----------------
template <int H>
__global__ void edge_exp_sum(const int* __restrict__ src, const int* __restrict__ dst,
                             float* __restrict__ e, const float* __restrict__ m,
                             float* __restrict__ ssum) {
    int ee = blockIdx.x * blockDim.x + threadIdx.x;
    if (ee >= EP) return;
    int d = (ee < EE) ? dst[ee] : ee - EE;
    #pragma unroll
    for (int h = 0; h < H; h++) {
        float ex = __expf(e[(size_t)ee * H + h] - m[d * H + h]);
        e[(size_t)ee * H + h] = ex;
        atomicAdd(&ssum[d * H + h], ex);
    }
}

// ---------------- edge pass C (layer1): scatter alpha * h[src] ----------------
// one warp per edge, 320 channels -> 10 per lane
__global__ void aggregate1(const int* __restrict__ src, const int* __restrict__ dst,
                           const float* __restrict__ e, const float* __restrict__ ssum,
                           const float* __restrict__ h, float* __restrict__ outz) {
    int g = blockIdx.x * blockDim.x + threadIdx.x;
    int w = g >> 5, lane = g & 31;
    if (w >= EP) return;
    int s = (w < EE) ? src[w] : w - EE;
    int d = (w < EE) ? dst[w] : w - EE;
    float alpha[H1];
    #pragma unroll
    for (int hh = 0; hh < H1; hh++)
        alpha[hh] = e[(size_t)w * H1 + hh] / (ssum[d * H1 + hh] + 1e-16f);
    const float* hs = h + (size_t)s * F1;
    float* od = outz + (size_t)d * F1;
    #pragma unroll
    for (int i = 0; i < F1 / 32; i++) {
        int c = i * 32 + lane;
        atomicAdd(&od[c], alpha[c >> 6] * hs[c]);
    }
}

// ---------------- edge pass C (layer2): H=1, C=64 ----------------
__global__ void aggregate2(const int* __restrict__ src, const int* __restrict__ dst,
                           const float* __restrict__ e, const float* __restrict__ ssum,
                           const float* __restrict__ h, float* __restrict__ outz) {
    int g = blockIdx.x * blockDim.x + threadIdx.x;
    int w = g >> 5, lane = g & 31;
    if (w >= EP) return;
    int s = (w < EE) ? src[w] : w - EE;
    int d = (w < EE) ? dst[w] : w - EE;
    float alpha = e[w] / (ssum[d] + 1e-16f);
    const float* hs = h + (size_t)s * OUTC;
    float* od = outz + (size_t)d * OUTC;
    atomicAdd(&od[lane],      alpha * hs[lane]);
    atomicAdd(&od[lane + 32], alpha * hs[lane + 32]);
}

// ---------------- bias + optional relu ----------------
__global__ void bias_relu(float* __restrict__ z, const float* __restrict__ b,
                          int total, int F) {
    int i = blockIdx.x * blockDim.x + threadIdx.x;
    if (i >= total) return;
    float v = z[i] + b[i % F];
    z[i] = (v > 0.0f) ? v : 0.0f;
}
__global__ void bias_only(float* __restrict__ z, const float* __restrict__ b,
                          int total, int F) {
    int i = blockIdx.x * blockDim.x + threadIdx.x;
    if (i >= total) return;
    z[i] = z[i] + b[i % F];
}

// ---------------- decode: warp per pair, 64-ch dot ----------------
__global__ void decode(const int* __restrict__ pos, const int* __restrict__ neg,
                       const float* __restrict__ z, float* __restrict__ out) {
    int g = blockIdx.x * blockDim.x + threadIdx.x;
    int p = g >> 5, lane = g & 31;
    if (p >= NPAIR) return;
    int i, j;
    if (p < PEC) { i = pos[p];        j = pos[PEC + p]; }
    else         { i = neg[p - PEC];  j = neg[PEC + p - PEC]; }
    const float* zi = z + (size_t)i * OUTC;
    const float* zj = z + (size_t)j * OUTC;
    float v = zi[lane] * zj[lane] + zi[lane + 32] * zj[lane + 32];
    #pragma unroll
    for (int o = 16; o > 0; o >>= 1) v += __shfl_down_sync(0xFFFFFFFFu, v, o);
    if (lane == 0) out[p] = v;
}

// ---------------- launch ----------------
extern "C" void kernel_launch(void* const* d_in, const int* in_sizes, int n_in,
                              void* d_out, int out_size) {
    const float* x      = (const float*)d_in[0];
    const int*   ei     = (const int*)  d_in[1];
    const int*   pos    = (const int*)  d_in[2];
    const int*   neg    = (const int*)  d_in[3];
    const float* W1     = (const float*)d_in[4];
    const float* att_s1 = (const float*)d_in[5];
    const float* att_d1 = (const float*)d_in[6];
    const float* b1     = (const float*)d_in[7];
    const float* W2     = (const float*)d_in[8];
    const float* att_s2 = (const float*)d_in[9];
    const float* att_d2 = (const float*)d_in[10];
    const float* b2     = (const float*)d_in[11];
    float* out = (float*)d_out;

    const int* src = ei;
    const int* dst = ei + EE;

    float *h1, *z1, *as1, *ad1, *m1, *s1, *e1;
    float *h2, *z2, *as2, *ad2, *m2, *s2, *e2;
    cudaGetSymbolAddress((void**)&h1, g_h1);
    cudaGetSymbolAddress((void**)&z1, g_z1);
    cudaGetSymbolAddress((void**)&as1, g_as1);
    cudaGetSymbolAddress((void**)&ad1, g_ad1);
    cudaGetSymbolAddress((void**)&m1, g_m1);
    cudaGetSymbolAddress((void**)&s1, g_s1);
    cudaGetSymbolAddress((void**)&e1, g_e1);
    cudaGetSymbolAddress((void**)&h2, g_h2);
    cudaGetSymbolAddress((void**)&z2, g_z2);
    cudaGetSymbolAddress((void**)&as2, g_as2);
    cudaGetSymbolAddress((void**)&ad2, g_ad2);
    cudaGetSymbolAddress((void**)&m2, g_m2);
    cudaGetSymbolAddress((void**)&s2, g_s2);
    cudaGetSymbolAddress((void**)&e2, g_e2);

    const int TPB = 256;

    // init accumulators / max / sum buffers (both layers)
    init_all<<<(NN * F1 + TPB - 1) / TPB, TPB>>>(z1, m1, s1, z2, m2, s2);

    // ---- layer 1 ----
    {
        dim3 grid((F1 + 63) / 64, (NN + 63) / 64);
        gemm64<<<grid, 256>>>(x, W1, h1, NN, F1, INC);
    }
    node_att<<<(NN * H1 + TPB - 1) / TPB, TPB>>>(h1, att_s1, att_d1, as1, ad1, H1, C1);
    edge_logits_max<H1><<<(EP + TPB - 1) / TPB, TPB>>>(src, dst, as1, ad1, e1, m1);
    edge_exp_sum<H1><<<(EP + TPB - 1) / TPB, TPB>>>(src, dst, e1, m1, s1);
    aggregate1<<<(EP * 32 + TPB - 1) / TPB, TPB>>>(src, dst, e1, s1, h1, z1);
    bias_relu<<<(NN * F1 + TPB - 1) / TPB, TPB>>>(z1, b1, NN * F1, F1);

    // ---- layer 2 ----
    {
        dim3 grid((OUTC + 63) / 64, (NN + 63) / 64);
        gemm64<<<grid, 256>>>(z1, W2, h2, NN, OUTC, F1);
    }
    node_att<<<(NN + TPB - 1) / TPB, TPB>>>(h2, att_s2, att_d2, as2, ad2, 1, OUTC);
    edge_logits_max<1><<<(EP + TPB - 1) / TPB, TPB>>>(src, dst, as2, ad2, e2, m2);
    edge_exp_sum<1><<<(EP + TPB - 1) / TPB, TPB>>>(src, dst, e2, m2, s2);
    aggregate2<<<(EP * 32 + TPB - 1) / TPB, TPB>>>(src, dst, e2, s2, h2, z2);
    bias_only<<<(NN * OUTC + TPB - 1) / TPB, TPB>>>(z2, b2, NN * OUTC, OUTC);

    // ---- decode ----
    decode<<<(NPAIR * 32 + TPB - 1) / TPB, TPB>>>(pos, neg, z2, out);
}

// round 2
// speedup vs baseline: 2.0470x; 2.0470x over previous
#include <cuda_runtime.h>
#include <math.h>

#define NN   30000
#define EE   480000
#define EP   (EE + NN)      // 510000 (edges + self loops)
#define INC  128
#define H1   5
#define C1   64
#define F1   (H1 * C1)      // 320
#define OUTC 64
#define PEC  100000
#define NPAIR (2 * PEC)
#define NEG_SLOPE 0.2f

#define SCAN_B 256
#define NBLK   ((NN + SCAN_B - 1) / SCAN_B)   // 118

// ---------------- scratch ----------------
__device__ float g_h1[NN * F1];
__device__ float g_z1[NN * F1];
__device__ float g_as1[NN * H1];
__device__ float g_ad1[NN * H1];
__device__ float g_h2[NN * OUTC];
__device__ float g_z2[NN * OUTC];
__device__ float g_as2[NN];
__device__ float g_ad2[NN];
__device__ int   g_cnt[NN];
__device__ int   g_rowptr[NN + 1];
__device__ int   g_part[NBLK];
__device__ int   g_cursor[NN];
__device__ int   g_csr_src[EP];

// ---------------- CSR build ----------------
__global__ void zero_cnt(int* cnt) {
    int i = blockIdx.x * blockDim.x + threadIdx.x;
    if (i < NN) cnt[i] = 0;
}

__global__ void hist(const int* __restrict__ dst, int* __restrict__ cnt) {
    int ee = blockIdx.x * blockDim.x + threadIdx.x;
    if (ee >= EP) return;
    int d = (ee < EE) ? dst[ee] : ee - EE;
    atomicAdd(&cnt[d], 1);
}

__global__ void scan1(const int* __restrict__ cnt, int* __restrict__ rowptr,
                      int* __restrict__ part) {
    __shared__ int sh[SCAN_B];
    int t = threadIdx.x;
    int i = blockIdx.x * SCAN_B + t;
    int v = (i < NN) ? cnt[i] : 0;
    sh[t] = v; __syncthreads();
    for (int o = 1; o < SCAN_B; o <<= 1) {
        int u = (t >= o) ? sh[t - o] : 0;
        __syncthreads();
        sh[t] += u;
        __syncthreads();
    }
    if (i < NN) rowptr[i] = sh[t] - v;          // exclusive within block
    if (t == SCAN_B - 1) part[blockIdx.x] = sh[t];
}

__global__ void scan2(int* __restrict__ part) {  // one block, 256 threads
    __shared__ int sh[256];
    int t = threadIdx.x;
    int v = (t < NBLK) ? part[t] : 0;
    sh[t] = v; __syncthreads();
    for (int o = 1; o < 256; o <<= 1) {
        int u = (t >= o) ? sh[t - o] : 0;
        __syncthreads();
        sh[t] += u;
        __syncthreads();
    }
    if (t < NBLK) part[t] = sh[t] - v;           // exclusive
}

__global__ void scan3(int* __restrict__ rowptr, const int* __restrict__ part,
                      int* __restrict__ cursor) {
    int i = blockIdx.x * SCAN_B + threadIdx.x;
    if (i < NN) {
        int v = rowptr[i] + part[blockIdx.x];
        rowptr[i] = v;
        cursor[i] = v;
    }
    if (i == 0) rowptr[NN] = EP;
}

__global__ void fill_csr(const int* __restrict__ src, const int* __restrict__ dst,
                         int* __restrict__ cursor, int* __restrict__ csr_src) {
    int ee = blockIdx.x * blockDim.x + threadIdx.x;
    if (ee >= EP) return;
    int s = (ee < EE) ? src[ee] : ee - EE;
    int d = (ee < EE) ? dst[ee] : ee - EE;
    int pos = atomicAdd(&cursor[d], 1);
    csr_src[pos] = s;
}

// ---------------- GEMM: C[M,Ncol] = A[M,K] @ B[K,Ncol], row-major ----------------
// BM=128, BN=64, BK=16, 256 threads, 8x4 microtile, float4 everywhere.
// Requires: K % 16 == 0, Ncol % 64 == 0.
__global__ void gemm128(const float* __restrict__ A, const float* __restrict__ B,
                        float* __restrict__ C, int M, int Ncol, int K) {
    const int BM = 128, BK = 16;
    __shared__ float As[BK][BM + 4];
    __shared__ float Bs[BK][64];
    const int tid = threadIdx.x;
    const int tx = tid & 15;        // N groups of 4
    const int ty = tid >> 4;        // M groups of 8
    const int row0 = blockIdx.y * BM;
    const int col0 = blockIdx.x * 64;

    const int ar = tid >> 2;             // 0..63
    const int kq = (tid & 3) * 4;        // 0,4,8,12
    const int kb = tid >> 4;             // 0..15
    const int c4 = (tid & 15) * 4;

    float acc[8][4] = {};

    for (int k0 = 0; k0 < K; k0 += BK) {
        #pragma unroll
        for (int rr = 0; rr < 2; rr++) {
            int r = ar + rr * 64;
            int gr = row0 + r;
            float4 v = (gr < M) ? *(const float4*)&A[(size_t)gr * K + k0 + kq]
                                : make_float4(0.f, 0.f, 0.f, 0.f);
            As[kq + 0][r] = v.x; As[kq + 1][r] = v.y;
            As[kq + 2][r] = v.z; As[kq + 3][r] = v.w;
        }
        *(float4*)&Bs[kb][c4] = *(const float4*)&B[(size_t)(k0 + kb) * Ncol + col0 + c4];
        __syncthreads();

        #pragma unroll
        for (int k = 0; k < BK; k++) {
            float ra[8], rb[4];
            *(float4*)&ra[0] = *(float4*)&As[k][ty * 8];
            *(float4*)&ra[4] = *(float4*)&As[k][ty * 8 + 4];
            *(float4*)&rb[0] = *(float4*)&Bs[k][tx * 4];
            #pragma unroll
            for (int i = 0; i < 8; i++)
                #pragma unroll
                for (int j = 0; j < 4; j++)
                    acc[i][j] += ra[i] * rb[j];
        }
        __syncthreads();
    }

    #pragma unroll
    for (int i = 0; i < 8; i++) {
        int r = row0 + ty * 8 + i;
        if (r < M)
            *(float4*)&C[(size_t)r * Ncol + col0 + tx * 4] = *(float4*)&acc[i][0];
    }
}

// ---------------- per-node attention logits ----------------
__global__ void node_att(const float* __restrict__ h,
                         const float* __restrict__ att_s,
                         const float* __restrict__ att_d,
                         float* __restrict__ as_, float* __restrict__ ad_,
                         int H, int C) {
    int idx = blockIdx.x * blockDim.x + threadIdx.x;
    if (idx >= NN * H) return;
    int n = idx / H, hd = idx % H;
    const float4* hr = (const float4*)(h + (size_t)n * H * C + (size_t)hd * C);
    const float4* sr = (const float4*)(att_s + (size_t)hd * C);
    const float4* dr = (const float4*)(att_d + (size_t)hd * C);
    float a = 0.f, b = 0.f;
    for (int i = 0; i < C / 4; i++) {
        float4 hv = hr[i], sv = sr[i], dv = dr[i];
        a += hv.x * sv.x + hv.y * sv.y + hv.z * sv.z + hv.w * sv.w;
        b += hv.x * dv.x + hv.y * dv.y + hv.z * dv.z + hv.w * dv.w;
    }
    as_[idx] = a;
    ad_[idx] = b;
}

// ---------------- fused softmax + aggregate, layer 1 ----------------
// block per dst node, 320 threads (one per output channel)
__global__ void agg1(const int* __restrict__ rowptr, const int* __restrict__ csr_src,
                     const float* __restrict__ as_, const float* __restrict__ ad_,
                     const float* __restrict__ h, const float* __restrict__ bias,
                     float* __restrict__ z) {
    __shared__ int   sh_src[32];
    __shared__ float sh_ex[H1 * 32];
    const int d = blockIdx.x;
    const int c = threadIdx.x;     // 0..319
    const int hh = c >> 6;
    const int start = rowptr[d], end = rowptr[d + 1];

    float acc = 0.f, sumex = 0.f;
    for (int j0 = start; j0 < end; j0 += 32) {
        int m = min(32, end - j0);
        if (c < H1 * 32) {
            int j = c & 31, hq = c >> 5;
            if (j < m) {
                int s = csr_src[j0 + j];
                if (hq == 0) sh_src[j] = s;
                float e = as_[s * H1 + hq] + ad_[d * H1 + hq];
                e = (e > 0.f) ? e : NEG_SLOPE * e;
                sh_ex[hq * 32 + j] = __expf(e);
            }
        }
        __syncthreads();
        #pragma unroll 4
        for (int j = 0; j < m; j++) {
            float ex = sh_ex[hh * 32 + j];
            sumex += ex;
            acc += ex * h[(size_t)sh_src[j] * F1 + c];
        }
        __syncthreads();
    }
    float v = acc / (sumex + 1e-16f) + bias[c];
    z[(size_t)d * F1 + c] = (v > 0.f) ? v : 0.f;   // fused relu
}

// ---------------- fused softmax + aggregate, layer 2 (H=1, C=64) ----------------
__global__ void agg2(const int* __restrict__ rowptr, const int* __restrict__ csr_src,
                     const float* __restrict__ as_, const float* __restrict__ ad_,
                     const float* __restrict__ h, const float* __restrict__ bias,
                     float* __restrict__ z) {
    __shared__ int   sh_src[32];
    __shared__ float sh_ex[32];
    const int d = blockIdx.x;
    const int c = threadIdx.x;     // 0..63
    const int start = rowptr[d], end = rowptr[d + 1];

    float acc = 0.f, sumex = 0.f;
    for (int j0 = start; j0 < end; j0 += 32) {
        int m = min(32, end - j0);
        if (c < 32 && c < m) {
            int s = csr_src[j0 + c];
            sh_src[c] = s;
            float e = as_[s] + ad_[d];
            e = (e > 0.f) ? e : NEG_SLOPE * e;
            sh_ex[c] = __expf(e);
        }
        __syncthreads();
        #pragma unroll 4
        for (int j = 0; j < m; j++) {
            float ex = sh_ex[j];
            sumex += ex;
            acc += ex * h[(size_t)sh_src[j] * OUTC + c];
        }
        __syncthreads();
    }
    z[(size_t)d * OUTC + c] = acc / (sumex + 1e-16f) + bias[c];
}

// ---------------- decode: warp per pair ----------------
__global__ void decode(const int* __restrict__ pos, const int* __restrict__ neg,
                       const float* __restrict__ z, float* __restrict__ out) {
    int g = blockIdx.x * blockDim.x + threadIdx.x;
    int p = g >> 5, lane = g & 31;
    if (p >= NPAIR) return;
    int i, j;
    if (p < PEC) { i = pos[p];       j = pos[PEC + p]; }
    else         { i = neg[p - PEC]; j = neg[PEC + p - PEC]; }
    const float* zi = z + (size_t)i * OUTC;
    const float* zj = z + (size_t)j * OUTC;
    float v = zi[lane] * zj[lane] + zi[lane + 32] * zj[lane + 32];
    #pragma unroll
    for (int o = 16; o > 0; o >>= 1) v += __shfl_down_sync(0xFFFFFFFFu, v, o);
    if (lane == 0) out[p] = v;
}

// ---------------- launch ----------------
extern "C" void kernel_launch(void* const* d_in, const int* in_sizes, int n_in,
                              void* d_out, int out_size) {
    const float* x      = (const float*)d_in[0];
    const int*   ei     = (const int*)  d_in[1];
    const int*   pos    = (const int*)  d_in[2];
    const int*   neg    = (const int*)  d_in[3];
    const float* W1     = (const float*)d_in[4];
    const float* att_s1 = (const float*)d_in[5];
    const float* att_d1 = (const float*)d_in[6];
    const float* b1     = (const float*)d_in[7];
    const float* W2     = (const float*)d_in[8];
    const float* att_s2 = (const float*)d_in[9];
    const float* att_d2 = (const float*)d_in[10];
    const float* b2     = (const float*)d_in[11];
    float* out = (float*)d_out;

    const int* src = ei;
    const int* dst = ei + EE;

    float *h1, *z1, *as1, *ad1, *h2, *z2, *as2, *ad2;
    int *cnt, *rowptr, *part, *cursor, *csr_src;
    cudaGetSymbolAddress((void**)&h1, g_h1);
    cudaGetSymbolAddress((void**)&z1, g_z1);
    cudaGetSymbolAddress((void**)&as1, g_as1);
    cudaGetSymbolAddress((void**)&ad1, g_ad1);
    cudaGetSymbolAddress((void**)&h2, g_h2);
    cudaGetSymbolAddress((void**)&z2, g_z2);
    cudaGetSymbolAddress((void**)&as2, g_as2);
    cudaGetSymbolAddress((void**)&ad2, g_ad2);
    cudaGetSymbolAddress((void**)&cnt, g_cnt);
    cudaGetSymbolAddress((void**)&rowptr, g_rowptr);
    cudaGetSymbolAddress((void**)&part, g_part);
    cudaGetSymbolAddress((void**)&cursor, g_cursor);
    cudaGetSymbolAddress((void**)&csr_src, g_csr_src);

    const int TPB = 256;

    // ---- CSR build (shared by both layers) ----
    zero_cnt<<<(NN + TPB - 1) / TPB, TPB>>>(cnt);
    hist<<<(EP + TPB - 1) / TPB, TPB>>>(dst, cnt);
    scan1<<<NBLK, SCAN_B>>>(cnt, rowptr, part);
    scan2<<<1, 256>>>(part);
    scan3<<<NBLK, SCAN_B>>>(rowptr, part, cursor);
    fill_csr<<<(EP + TPB - 1) / TPB, TPB>>>(src, dst, cursor, csr_src);

    // ---- layer 1 ----
    {
        dim3 grid(F1 / 64, (NN + 127) / 128);
        gemm128<<<grid, 256>>>(x, W1, h1, NN, F1, INC);
    }
    node_att<<<(NN * H1 + TPB - 1) / TPB, TPB>>>(h1, att_s1, att_d1, as1, ad1, H1, C1);
    agg1<<<NN, F1>>>(rowptr, csr_src, as1, ad1, h1, b1, z1);

    // ---- layer 2 ----
    {
        dim3 grid(OUTC / 64, (NN + 127) / 128);
        gemm128<<<grid, 256>>>(z1, W2, h2, NN, OUTC, F1);
    }
    node_att<<<(NN + TPB - 1) / TPB, TPB>>>(h2, att_s2, att_d2, as2, ad2, 1, OUTC);
    agg2<<<NN, OUTC>>>(rowptr, csr_src, as2, ad2, h2, b2, z2);

    // ---- decode ----
    decode<<<(NPAIR * 32 + TPB - 1) / TPB, TPB>>>(pos, neg, z2, out);
}

// round 4
// speedup vs baseline: 2.1076x; 1.0296x over previous
#include <cuda_runtime.h>
#include <cuda_bf16.h>
#include <math.h>
#include <stdint.h>

#define NN   30000
#define EE   480000
#define EP   (EE + NN)      // 510000 (edges + self loops)
#define INC  128
#define H1   5
#define C1   64
#define F1   (H1 * C1)      // 320
#define OUTC 64
#define PEC  100000
#define NPAIR (2 * PEC)
#define NEG_SLOPE 0.2f

#define SCAN_B 256
#define NBLK   ((NN + SCAN_B - 1) / SCAN_B)   // 118

// ---------------- scratch ----------------
__device__ float g_h1[NN * F1];
__device__ float g_z1[NN * F1];
__device__ float g_as1[NN * H1];
__device__ float g_ad1[NN * H1];
__device__ float g_h2[NN * OUTC];
__device__ float g_z2[NN * OUTC];
__device__ float g_as2[NN];
__device__ float g_ad2[NN];
__device__ int   g_cnt[NN];
__device__ int   g_rowptr[NN + 1];
__device__ int   g_part[NBLK];
__device__ int   g_cursor[NN];
__device__ int   g_csr_src[EP];
// split-bf16 operands
__device__ __nv_bfloat16 g_xh[NN * INC];
__device__ __nv_bfloat16 g_xl[NN * INC];
__device__ __nv_bfloat16 g_z1h[NN * F1];
__device__ __nv_bfloat16 g_z1l[NN * F1];
__device__ __nv_bfloat16 g_w1h[F1 * INC];   // W1^T [320,128]
__device__ __nv_bfloat16 g_w1l[F1 * INC];
__device__ __nv_bfloat16 g_w2h[OUTC * F1];  // W2^T [64,320]
__device__ __nv_bfloat16 g_w2l[OUTC * F1];

// ---------------- mma helpers (base PTX, sm_80+: compiles for sm_103) --------
__device__ __forceinline__ uint32_t smem_u32(const void* p) {
    uint32_t a;
    asm("{ .reg .u64 t; cvta.to.shared.u64 t, %1; cvt.u32.u64 %0, t; }" : "=r"(a) : "l"(p));
    return a;
}
__device__ __forceinline__ void ldsm_x4(uint32_t& r0, uint32_t& r1, uint32_t& r2,
                                        uint32_t& r3, uint32_t addr) {
    asm volatile("ldmatrix.sync.aligned.m8n8.x4.shared.b16 {%0,%1,%2,%3}, [%4];"
                 : "=r"(r0), "=r"(r1), "=r"(r2), "=r"(r3) : "r"(addr));
}
__device__ __forceinline__ void mma_bf16(float* c, const uint32_t* a, const uint32_t* b) {
    asm volatile(
        "mma.sync.aligned.m16n8k16.row.col.f32.bf16.bf16.f32 "
        "{%0,%1,%2,%3}, {%4,%5,%6,%7}, {%8,%9}, {%0,%1,%2,%3};"
        : "+f"(c[0]), "+f"(c[1]), "+f"(c[2]), "+f"(c[3])
        : "r"(a[0]), "r"(a[1]), "r"(a[2]), "r"(a[3]), "r"(b[0]), "r"(b[1]));
}

// ---------------- CSR build ----------------
__global__ void zero_cnt(int* cnt) {
    int i = blockIdx.x * blockDim.x + threadIdx.x;
    if (i < NN) cnt[i] = 0;
}
__global__ void hist(const int* __restrict__ dst, int* __restrict__ cnt) {
    int ee = blockIdx.x * blockDim.x + threadIdx.x;
    if (ee >= EP) return;
    int d = (ee < EE) ? dst[ee] : ee - EE;
    atomicAdd(&cnt[d], 1);
}
__global__ void scan1(const int* __restrict__ cnt, int* __restrict__ rowptr,
                      int* __restrict__ part) {
    __shared__ int sh[SCAN_B];
    int t = threadIdx.x;
    int i = blockIdx.x * SCAN_B + t;
    int v = (i < NN) ? cnt[i] : 0;
    sh[t] = v; __syncthreads();
    for (int o = 1; o < SCAN_B; o <<= 1) {
        int u = (t >= o) ? sh[t - o] : 0;
        __syncthreads(); sh[t] += u; __syncthreads();
    }
    if (i < NN) rowptr[i] = sh[t] - v;
    if (t == SCAN_B - 1) part[blockIdx.x] = sh[t];
}
__global__ void scan2(int* __restrict__ part) {
    __shared__ int sh[256];
    int t = threadIdx.x;
    int v = (t < NBLK) ? part[t] : 0;
    sh[t] = v; __syncthreads();
    for (int o = 1; o < 256; o <<= 1) {
        int u = (t >= o) ? sh[t - o] : 0;
        __syncthreads(); sh[t] += u; __syncthreads();
    }
    if (t < NBLK) part[t] = sh[t] - v;
}
__global__ void scan3(int* __restrict__ rowptr, const int* __restrict__ part,
                      int* __restrict__ cursor) {
    int i = blockIdx.x * SCAN_B + threadIdx.x;
    if (i < NN) {
        int v = rowptr[i] + part[blockIdx.x];
        rowptr[i] = v; cursor[i] = v;
    }
    if (i == 0) rowptr[NN] = EP;
}
__global__ void fill_csr(const int* __restrict__ src, const int* __restrict__ dst,
                         int* __restrict__ cursor, int* __restrict__ csr_src) {
    int ee = blockIdx.x * blockDim.x + threadIdx.x;
    if (ee >= EP) return;
    int s = (ee < EE) ? src[ee] : ee - EE;
    int d = (ee < EE) ? dst[ee] : ee - EE;
    int pos = atomicAdd(&cursor[d], 1);
    csr_src[pos] = s;
}

// ---------------- split fp32 -> bf16 hi + bf16 lo ----------------
__global__ void split_hilo(const float* __restrict__ in, __nv_bfloat16* __restrict__ hi,
                           __nv_bfloat16* __restrict__ lo, int n) {
    int i = blockIdx.x * blockDim.x + threadIdx.x;
    if (i >= n) return;
    float v = in[i];
    __nv_bfloat16 h = __float2bfloat16(v);
    hi[i] = h;
    lo[i] = __float2bfloat16(v - __bfloat162float(h));
}
// out[n*K + k] = W[k*Ncol + n], split
__global__ void splitT_hilo(const float* __restrict__ W, __nv_bfloat16* __restrict__ hi,
                            __nv_bfloat16* __restrict__ lo, int K, int Ncol) {
    int i = blockIdx.x * blockDim.x + threadIdx.x;
    if (i >= K * Ncol) return;
    int n = i / K, k = i % K;
    float v = W[(size_t)k * Ncol + n];
    __nv_bfloat16 h = __float2bfloat16(v);
    hi[i] = h;
    lo[i] = __float2bfloat16(v - __bfloat162float(h));
}

// ---------------- HMMA split-bf16 GEMM ----------------
// C[M,Ncol] = Ah@Bh^T + Al@Bh^T + Ah@Bl^T, A [M,K] bf16 row-major,
// B stored [Ncol,K] bf16 row-major (i.e. K-major both).
// CTA: 256 threads, 128x64 tile, warps 4(M) x 2(N), warp tile 32x32.
#define STR 72                      // padded SMEM row stride (bf16 elems)
#define SM_AH 0
#define SM_AL (128 * STR)
#define SM_BH (2 * 128 * STR)
#define SM_BL (2 * 128 * STR + 64 * STR)
#define SM_ELEMS (2 * 128 * STR + 2 * 64 * STR)   // 27648 bf16 = 55296 B

__global__ void __launch_bounds__(256, 3) mma_gemm(
    const __nv_bfloat16* __restrict__ Ah, const __nv_bfloat16* __restrict__ Al,
    const __nv_bfloat16* __restrict__ Bh, const __nv_bfloat16* __restrict__ Bl,
    float* __restrict__ C, int M, int Ncol, int K)
{
    extern __shared__ __align__(16) __nv_bfloat16 smem[];
    const int tid = threadIdx.x;
    const int wid = tid >> 5, lane = tid & 31;
    const int wm = wid >> 1;            // 0..3
    const int wn = wid & 1;             // 0..1
    const int row0 = blockIdx.y * 128;
    const int col0 = blockIdx.x * 64;
    const uint32_t sb = smem_u32(smem);

    float acc[2][4][4];
    #pragma unroll
    for (int i = 0; i < 2; i++)
        #pragma unroll
        for (int j = 0; j < 4; j++)
            #pragma unroll
            for (int q = 0; q < 4; q++) acc[i][j][q] = 0.f;

    // per-thread ldmatrix source coordinates (element offsets within tiles)
    const int a_row = lane & 15;
    const int a_koff = (lane >> 4) * 8;
    const int b_row = (lane & 7) + ((lane >> 4) << 3);
    const int b_koff = ((lane >> 3) & 1) * 8;

    for (int K0 = 0; K0 < K; K0 += 64) {
        // stage A chunk 128x64 (hi+lo): 1024 uint4 units each
        #pragma unroll
        for (int i = 0; i < 4; i++) {
            int u = tid + i * 256;
            int r = u >> 3, c8 = (u & 7) * 8;
            int dstoff = r * STR + c8;
            int gr = row0 + r;
            uint4 vh, vl;
            if (gr < M) {
                vh = *(const uint4*)(Ah + (size_t)gr * K + K0 + c8);
                vl = *(const uint4*)(Al + (size_t)gr * K + K0 + c8);
            } else { vh = make_uint4(0u, 0u, 0u, 0u); vl = vh; }
            *(uint4*)(smem + SM_AH + dstoff) = vh;
            *(uint4*)(smem + SM_AL + dstoff) = vl;
        }
        // stage B chunk 64x64 (hi+lo): 512 units each
        #pragma unroll
        for (int i = 0; i < 2; i++) {
            int u = tid + i * 256;
            int r = u >> 3, c8 = (u & 7) * 8;
            int dstoff = r * STR + c8;
            const __nv_bfloat16* ph = Bh + (size_t)(col0 + r) * K + K0 + c8;
            const __nv_bfloat16* pl = Bl + (size_t)(col0 + r) * K + K0 + c8;
            *(uint4*)(smem + SM_BH + dstoff) = *(const uint4*)ph;
            *(uint4*)(smem + SM_BL + dstoff) = *(const uint4*)pl;
        }
        __syncthreads();

        #pragma unroll
        for (int ks = 0; ks < 4; ks++) {
            uint32_t ah[2][4], al[2][4], bh[4][2], bl[4][2];
            #pragma unroll
            for (int mi = 0; mi < 2; mi++) {
                int off = (wm * 32 + mi * 16 + a_row) * STR + ks * 16 + a_koff;
                ldsm_x4(ah[mi][0], ah[mi][1], ah[mi][2], ah[mi][3],
                        sb + (uint32_t)(SM_AH + off) * 2);
                ldsm_x4(al[mi][0], al[mi][1], al[mi][2], al[mi][3],
                        sb + (uint32_t)(SM_AL + off) * 2);
            }
            #pragma unroll
            for (int np = 0; np < 2; np++) {
                int off = (wn * 32 + np * 16 + b_row) * STR + ks * 16 + b_koff;
                ldsm_x4(bh[np * 2][0], bh[np * 2][1], bh[np * 2 + 1][0], bh[np * 2 + 1][1],
                        sb + (uint32_t)(SM_BH + off) * 2);
                ldsm_x4(bl[np * 2][0], bl[np * 2][1], bl[np * 2 + 1][0], bl[np * 2 + 1][1],
                        sb + (uint32_t)(SM_BL + off) * 2);
            }
            #pragma unroll
            for (int mi = 0; mi < 2; mi++)
                #pragma unroll
                for (int ni = 0; ni < 4; ni++) {
                    mma_bf16(acc[mi][ni], ah[mi], bh[ni]);   // ah*bh
                    mma_bf16(acc[mi][ni], al[mi], bh[ni]);   // al*bh
                    mma_bf16(acc[mi][ni], ah[mi], bl[ni]);   // ah*bl
                }
        }
        __syncthreads();
    }

    // epilogue: c0,c1 -> (row = lane/4, col = 2*(lane%4)); c2,c3 -> row+8
    const int erow = lane >> 2;
    const int ecol = (lane & 3) * 2;
    #pragma unroll
    for (int mi = 0; mi < 2; mi++) {
        int r0 = row0 + wm * 32 + mi * 16 + erow;
        #pragma unroll
        for (int ni = 0; ni < 4; ni++) {
            int cc = col0 + wn * 32 + ni * 8 + ecol;
            if (r0 < M)
                *(float2*)&C[(size_t)r0 * Ncol + cc] = make_float2(acc[mi][ni][0], acc[mi][ni][1]);
            if (r0 + 8 < M)
                *(float2*)&C[(size_t)(r0 + 8) * Ncol + cc] = make_float2(acc[mi][ni][2], acc[mi][ni][3]);
        }
    }
}

// ---------------- per-node attention logits ----------------
__global__ void node_att(const float* __restrict__ h,
                         const float* __restrict__ att_s,
                         const float* __restrict__ att_d,
                         float* __restrict__ as_, float* __restrict__ ad_,
                         int H, int C) {
    int idx = blockIdx.x * blockDim.x + threadIdx.x;
    if (idx >= NN * H) return;
    int n = idx / H, hd = idx % H;
    const float4* hr = (const float4*)(h + (size_t)n * H * C + (size_t)hd * C);
    const float4* sr = (const float4*)(att_s + (size_t)hd * C);
    const float4* dr = (const float4*)(att_d + (size_t)hd * C);
    float a = 0.f, b = 0.f;
    for (int i = 0; i < C / 4; i++) {
        float4 hv = hr[i], sv = sr[i], dv = dr[i];
        a += hv.x * sv.x + hv.y * sv.y + hv.z * sv.z + hv.w * sv.w;
        b += hv.x * dv.x + hv.y * dv.y + hv.z * dv.z + hv.w * dv.w;
    }
    as_[idx] = a;
    ad_[idx] = b;
}

// ---------------- fused softmax + aggregate, layer 1 ----------------
__global__ void agg1(const int* __restrict__ rowptr, const int* __restrict__ csr_src,
                     const float* __restrict__ as_, const float* __restrict__ ad_,
                     const float* __restrict__ h, const float* __restrict__ bias,
                     float* __restrict__ z) {
    __shared__ int   sh_src[32];
    __shared__ float sh_ex[H1 * 32];
    const int d = blockIdx.x;
    const int c = threadIdx.x;     // 0..319
    const int hh = c >> 6;
    const int start = rowptr[d], end = rowptr[d + 1];

    float acc = 0.f, sumex = 0.f;
    for (int j0 = start; j0 < end; j0 += 32) {
        int m = min(32, end - j0);
        if (c < H1 * 32) {
            int j = c & 31, hq = c >> 5;
            if (j < m) {
                int s = csr_src[j0 + j];
                if (hq == 0) sh_src[j] = s;
                float e = as_[s * H1 + hq] + ad_[d * H1 + hq];
                e = (e > 0.f) ? e : NEG_SLOPE * e;
                sh_ex[hq * 32 + j] = __expf(e);
            }
        }
        __syncthreads();
        #pragma unroll 4
        for (int j = 0; j < m; j++) {
            float ex = sh_ex[hh * 32 + j];
            sumex += ex;
            acc += ex * h[(size_t)sh_src[j] * F1 + c];
        }
        __syncthreads();
    }
    float v = acc / (sumex + 1e-16f) + bias[c];
    z[(size_t)d * F1 + c] = (v > 0.f) ? v : 0.f;
}

// ---------------- fused softmax + aggregate, layer 2 ----------------
__global__ void agg2(const int* __restrict__ rowptr, const int* __restrict__ csr_src,
                     const float* __restrict__ as_, const float* __restrict__ ad_,
                     const float* __restrict__ h, const float* __restrict__ bias,
                     float* __restrict__ z) {
    __shared__ int   sh_src[32];
    __shared__ float sh_ex[32];
    const int d = blockIdx.x;
    const int c = threadIdx.x;     // 0..63
    const int start = rowptr[d], end = rowptr[d + 1];

    float acc = 0.f, sumex = 0.f;
    for (int j0 = start; j0 < end; j0 += 32) {
        int m = min(32, end - j0);
        if (c < 32 && c < m) {
            int s = csr_src[j0 + c];
            sh_src[c] = s;
            float e = as_[s] + ad_[d];
            e = (e > 0.f) ? e : NEG_SLOPE * e;
            sh_ex[c] = __expf(e);
        }
        __syncthreads();
        #pragma unroll 4
        for (int j = 0; j < m; j++) {
            float ex = sh_ex[j];
            sumex += ex;
            acc += ex * h[(size_t)sh_src[j] * OUTC + c];
        }
        __syncthreads();
    }
    z[(size_t)d * OUTC + c] = acc / (sumex + 1e-16f) + bias[c];
}

// ---------------- decode ----------------
__global__ void decode(const int* __restrict__ pos, const int* __restrict__ neg,
                       const float* __restrict__ z, float* __restrict__ out) {
    int g = blockIdx.x * blockDim.x + threadIdx.x;
    int p = g >> 5, lane = g & 31;
    if (p >= NPAIR) return;
    int i, j;
    if (p < PEC) { i = pos[p];       j = pos[PEC + p]; }
    else         { i = neg[p - PEC]; j = neg[PEC + p - PEC]; }
    const float* zi = z + (size_t)i * OUTC;
    const float* zj = z + (size_t)j * OUTC;
    float v = zi[lane] * zj[lane] + zi[lane + 32] * zj[lane + 32];
    #pragma unroll
    for (int o = 16; o > 0; o >>= 1) v += __shfl_down_sync(0xFFFFFFFFu, v, o);
    if (lane == 0) out[p] = v;
}

// ---------------- launch ----------------
extern "C" void kernel_launch(void* const* d_in, const int* in_sizes, int n_in,
                              void* d_out, int out_size) {
    const float* x      = (const float*)d_in[0];
    const int*   ei     = (const int*)  d_in[1];
    const int*   pos    = (const int*)  d_in[2];
    const int*   neg    = (const int*)  d_in[3];
    const float* W1     = (const float*)d_in[4];
    const float* att_s1 = (const float*)d_in[5];
    const float* att_d1 = (const float*)d_in[6];
    const float* b1     = (const float*)d_in[7];
    const float* W2     = (const float*)d_in[8];
    const float* att_s2 = (const float*)d_in[9];
    const float* att_d2 = (const float*)d_in[10];
    const float* b2     = (const float*)d_in[11];
    float* out = (float*)d_out;

    const int* src = ei;
    const int* dst = ei + EE;

    float *h1, *z1, *as1, *ad1, *h2, *z2, *as2, *ad2;
    int *cnt, *rowptr, *part, *cursor, *csr_src;
    __nv_bfloat16 *xh, *xl, *z1h, *z1l, *w1h, *w1l, *w2h, *w2l;
    cudaGetSymbolAddress((void**)&h1, g_h1);
    cudaGetSymbolAddress((void**)&z1, g_z1);
    cudaGetSymbolAddress((void**)&as1, g_as1);
    cudaGetSymbolAddress((void**)&ad1, g_ad1);
    cudaGetSymbolAddress((void**)&h2, g_h2);
    cudaGetSymbolAddress((void**)&z2, g_z2);
    cudaGetSymbolAddress((void**)&as2, g_as2);
    cudaGetSymbolAddress((void**)&ad2, g_ad2);
    cudaGetSymbolAddress((void**)&cnt, g_cnt);
    cudaGetSymbolAddress((void**)&rowptr, g_rowptr);
    cudaGetSymbolAddress((void**)&part, g_part);
    cudaGetSymbolAddress((void**)&cursor, g_cursor);
    cudaGetSymbolAddress((void**)&csr_src, g_csr_src);
    cudaGetSymbolAddress((void**)&xh, g_xh);
    cudaGetSymbolAddress((void**)&xl, g_xl);
    cudaGetSymbolAddress((void**)&z1h, g_z1h);
    cudaGetSymbolAddress((void**)&z1l, g_z1l);
    cudaGetSymbolAddress((void**)&w1h, g_w1h);
    cudaGetSymbolAddress((void**)&w1l, g_w1l);
    cudaGetSymbolAddress((void**)&w2h, g_w2h);
    cudaGetSymbolAddress((void**)&w2l, g_w2l);

    const int TPB = 256;
    constexpr int SMEM_GEMM = SM_ELEMS * 2;   // 55296 bytes
    cudaFuncSetAttribute(mma_gemm, cudaFuncAttributeMaxDynamicSharedMemorySize, SMEM_GEMM);

    // ---- CSR build ----
    zero_cnt<<<(NN + TPB - 1) / TPB, TPB>>>(cnt);
    hist<<<(EP + TPB - 1) / TPB, TPB>>>(dst, cnt);
    scan1<<<NBLK, SCAN_B>>>(cnt, rowptr, part);
    scan2<<<1, 256>>>(part);
    scan3<<<NBLK, SCAN_B>>>(rowptr, part, cursor);
    fill_csr<<<(EP + TPB - 1) / TPB, TPB>>>(src, dst, cursor, csr_src);

    // ---- operand prep ----
    split_hilo<<<(NN * INC + TPB - 1) / TPB, TPB>>>(x, xh, xl, NN * INC);
    splitT_hilo<<<(INC * F1 + TPB - 1) / TPB, TPB>>>(W1, w1h, w1l, INC, F1);
    splitT_hilo<<<(F1 * OUTC + TPB - 1) / TPB, TPB>>>(W2, w2h, w2l, F1, OUTC);

    // ---- layer 1 ----
    {
        dim3 grid(F1 / 64, (NN + 127) / 128);   // (5, 235)
        mma_gemm<<<grid, 256, SMEM_GEMM>>>(xh, xl, w1h, w1l, h1, NN, F1, INC);
    }
    node_att<<<(NN * H1 + TPB - 1) / TPB, TPB>>>(h1, att_s1, att_d1, as1, ad1, H1, C1);
    agg1<<<NN, F1>>>(rowptr, csr_src, as1, ad1, h1, b1, z1);

    // ---- layer 2 ----
    split_hilo<<<(NN * F1 + TPB - 1) / TPB, TPB>>>(z1, z1h, z1l, NN * F1);
    {
        dim3 grid(1, (NN + 127) / 128);          // (1, 235)
        mma_gemm<<<grid, 256, SMEM_GEMM>>>(z1h, z1l, w2h, w2l, h2, NN, OUTC, F1);
    }
    node_att<<<(NN + TPB - 1) / TPB, TPB>>>(h2, att_s2, att_d2, as2, ad2, 1, OUTC);
    agg2<<<NN, OUTC>>>(rowptr, csr_src, as2, ad2, h2, b2, z2);

    // ---- decode ----
    decode<<<(NPAIR * 32 + TPB - 1) / TPB, TPB>>>(pos, neg, z2, out);
}